// round 2
// baseline (speedup 1.0000x reference)
#include <cuda_runtime.h>
#include <cstdint>

// ---------------------------------------------------------------------------
// FeatureLevel: fake-quant (16 levels) of two feature grids + gather.
//   g0: [1,8,2048,2048] -> 4-corner raw gather (32 feats)
//   g1: [1,8,1024,1024] -> bilinear grid_sample, zeros pad (8 feats)
//   out: [N,40] f32, N = 2,097,152
//
// R2: pair-packed code tables (ulonglong2 per texel = codes for x and x+1,
// one LDG.128 per row-tap instead of two LDG.64) + shared-memory staged
// coalesced streaming stores. Cuts gather L1tex wavefronts ~3.4x.
// ---------------------------------------------------------------------------

#define R0 2048
#define R1 1024
#define CCH 8
#define TPB 256
#define SSTRIDE 41   // 40 floats/point + 1 pad word -> conflict-free smem

// Scratch (no cudaMalloc allowed): pair-packed code tables.
// pairs[y*RES + x] = { codes(y,x), codes(y,x+1) }   (16B aligned)
__device__ ulonglong2 g_pairs0[(size_t)R0 * R0];   // 64 MB
__device__ ulonglong2 g_pairs1[(size_t)R1 * R1];   // 16 MB

__device__ __forceinline__ float dq(unsigned c) {
    // exact: c/16 - 15/32
    return fmaf((float)c, 0.0625f, -0.46875f);
}

__device__ __forceinline__ unsigned qcode(float x) {
    // codes = clip(round((x - lo)/q), 0, 15); lo = -0.46875, 1/q = 16 (exact)
    float c = rintf(__fmul_rn(__fadd_rn(x, 0.46875f), 16.0f));
    c = fminf(fmaxf(c, 0.0f), 15.0f);
    return (unsigned)c;
}

template <int RES>
__device__ __forceinline__ unsigned long long pack_codes(const float* __restrict__ g,
                                                         size_t idx) {
    const size_t plane = (size_t)RES * RES;
    unsigned long long packed = 0;
#pragma unroll
    for (int c = 0; c < CCH; c++) {
        float x = __ldg(g + (size_t)c * plane + idx);
        packed |= ((unsigned long long)qcode(x)) << (8 * c);
    }
    return packed;
}

// Quantize + transpose [C,H,W] -> pair-packed [H*W] ulonglong2.
template <int RES>
__global__ __launch_bounds__(TPB) void quant_pack_pairs_kernel(
    const float* __restrict__ g, ulonglong2* __restrict__ pairs) {
    size_t idx = (size_t)blockIdx.x * TPB + threadIdx.x;   // RES*RES % TPB == 0
    unsigned long long a = pack_codes<RES>(g, idx);
    unsigned long long b = __shfl_down_sync(0xFFFFFFFFu, a, 1);
    if ((threadIdx.x & 31) == 31) {
        size_t j = (idx + 1 < (size_t)RES * RES) ? idx + 1 : idx;
        b = pack_codes<RES>(g, j);
    }
    pairs[idx] = make_ulonglong2(a, b);
}

__global__ __launch_bounds__(TPB) void gather_kernel(
    const float2* __restrict__ uv, float* __restrict__ out, int n) {
    __shared__ float buf[TPB * SSTRIDE];
    int i = blockIdx.x * TPB + threadIdx.x;
    int ic = min(i, n - 1);

    float2 p = __ldcs(&uv[ic]);
    float* row = buf + threadIdx.x * SSTRIDE;

    // ---------------- G0: 4-neighbor raw gather ----------------
    float px = __fadd_rn(__fmul_rn(p.x, (float)R0), -0.5f);
    float py = __fadd_rn(__fmul_rn(p.y, (float)R0), -0.5f);
    int x0 = (int)fminf(fmaxf(floorf(px), 0.0f), (float)(R0 - 2));
    int y0 = (int)fminf(fmaxf(floorf(py), 0.0f), (float)(R0 - 2));

    ulonglong2 pr0 = __ldg(&g_pairs0[(size_t)y0 * R0 + x0]);        // (x0,x1)@y0
    ulonglong2 pr1 = __ldg(&g_pairs0[(size_t)(y0 + 1) * R0 + x0]);  // (x0,x1)@y1
#pragma unroll
    for (int c = 0; c < CCH; c++) {
        row[c]      = dq((unsigned)(pr0.x >> (8 * c)) & 0xFFu);
        row[8 + c]  = dq((unsigned)(pr0.y >> (8 * c)) & 0xFFu);
        row[16 + c] = dq((unsigned)(pr1.x >> (8 * c)) & 0xFFu);
        row[24 + c] = dq((unsigned)(pr1.y >> (8 * c)) & 0xFFu);
    }

    // ---------------- G1: bilinear grid_sample (zeros pad) ----------------
    // Replicate reference op order exactly (no FMA contraction in index math).
    float gx = __fadd_rn(__fmul_rn(p.x, 2.0f), -1.0f);
    float gy = __fadd_rn(__fmul_rn(p.y, 2.0f), -1.0f);
    float ix = __fadd_rn(__fmul_rn(__fmul_rn(__fadd_rn(gx, 1.0f), 0.5f), (float)R1), -0.5f);
    float iy = __fadd_rn(__fmul_rn(__fmul_rn(__fadd_rn(gy, 1.0f), 0.5f), (float)R1), -0.5f);

    float fx0 = floorf(ix), fy0 = floorf(iy);
    float wx1 = __fadd_rn(ix, -fx0);
    float wy1 = __fadd_rn(iy, -fy0);
    float wx0 = __fadd_rn(1.0f, -wx1);
    float wy0 = __fadd_rn(1.0f, -wy1);

    int jx0 = (int)fx0, jy0 = (int)fy0;
    int jx1 = jx0 + 1, jy1 = jy0 + 1;
    // uv in [0,1): jx0,jy0 in [-1,1023]; jx1,jy1 in [0,1024]
    bool vx0 = jx0 >= 0;
    bool vx1 = jx1 <= R1 - 1;
    bool vy0 = jy0 >= 0;
    bool vy1 = jy1 <= R1 - 1;

    float m00 = (vx0 & vy0) ? __fmul_rn(wx0, wy0) : 0.0f;
    float m10 = (vx1 & vy0) ? __fmul_rn(wx1, wy0) : 0.0f;
    float m01 = (vx0 & vy1) ? __fmul_rn(wx0, wy1) : 0.0f;
    float m11 = (vx1 & vy1) ? __fmul_rn(wx1, wy1) : 0.0f;

    int jc  = min(max(jx0, 0), R1 - 1);
    int ry0 = min(max(jy0, 0), R1 - 1);
    int ry1 = min(max(jy1, 0), R1 - 1);

    ulonglong2 q0 = __ldg(&g_pairs1[(size_t)ry0 * R1 + jc]);
    ulonglong2 q1 = __ldg(&g_pairs1[(size_t)ry1 * R1 + jc]);
    // tap values: x0 tap = .x ; x1 tap = .y, except jx0==-1 where x1 maps to col 0 = .x
    unsigned long long t00 = q0.x;
    unsigned long long t10 = (jx0 < 0) ? q0.x : q0.y;
    unsigned long long t01 = q1.x;
    unsigned long long t11 = (jx0 < 0) ? q1.x : q1.y;

#pragma unroll
    for (int c = 0; c < CCH; c++) {
        float acc = 0.0f;
        acc = fmaf(dq((unsigned)(t00 >> (8 * c)) & 0xFFu), m00, acc);
        acc = fmaf(dq((unsigned)(t10 >> (8 * c)) & 0xFFu), m10, acc);
        acc = fmaf(dq((unsigned)(t01 >> (8 * c)) & 0xFFu), m01, acc);
        acc = fmaf(dq((unsigned)(t11 >> (8 * c)) & 0xFFu), m11, acc);
        row[32 + c] = acc;
    }

    __syncthreads();

    // ---------------- coalesced streaming store ----------------
    size_t base = (size_t)blockIdx.x * TPB * 40;
    size_t total = (size_t)n * 40;
#pragma unroll
    for (int k = 0; k < 40; k++) {
        int f = k * TPB + threadIdx.x;        // 0 .. 10239
        int pp = f / 40;
        int cc = f - pp * 40;
        size_t g = base + f;
        if (g < total) __stcs(out + g, buf[pp * SSTRIDE + cc]);
    }
}

extern "C" void kernel_launch(void* const* d_in, const int* in_sizes, int n_in,
                              void* d_out, int out_size) {
    const float* uv = (const float*)d_in[0];
    const float* g0 = (const float*)d_in[1];
    const float* g1 = (const float*)d_in[2];
    float* out = (float*)d_out;

    int n = in_sizes[0] / 2;

    ulonglong2* p0;
    ulonglong2* p1;
    cudaGetSymbolAddress((void**)&p0, g_pairs0);
    cudaGetSymbolAddress((void**)&p1, g_pairs1);

    quant_pack_pairs_kernel<R0><<<(R0 * R0) / TPB, TPB>>>(g0, p0);
    quant_pack_pairs_kernel<R1><<<(R1 * R1) / TPB, TPB>>>(g1, p1);

    gather_kernel<<<(n + TPB - 1) / TPB, TPB>>>((const float2*)uv, out, n);
}

// round 5
// speedup vs baseline: 1.3005x; 1.3005x over previous
#include <cuda_runtime.h>
#include <cstdint>

// ---------------------------------------------------------------------------
// FeatureLevel: fake-quant (16 levels) of two grids + gather.
//   g0: [1,8,2048,2048] -> 4-corner raw gather (32 feats)
//   g1: [1,8,1024,1024] -> bilinear grid_sample, zeros pad (8 feats)
//   out: [N,40] f32, N = 2,097,152
//
// R3 resubmit #2 (two broker timeouts in a row; kernel has never run):
// 4-bit codes -> one u32 per texel, x-adjacent PAIR packed in one u64.
// Tables are 42MB total (L2-resident) and one LDG.64 per row-tap returns
// both x-neighbors. Output staged in smem -> coalesced streaming stores.
// ---------------------------------------------------------------------------

#define R0 2048
#define R1 1024
#define CCH 8
#define QTPB 256
#define TPB 320          // multiple of 40: store index math is loop-invariant
#define SSTRIDE 41       // 40 floats + 1 pad -> conflict-free smem

// Pair-packed 4-bit code tables: word[y*RES+x] = {lo: codes(y,x), hi: codes(y,x+1)}
__device__ unsigned long long g_pairs0[(size_t)R0 * R0];   // 33.5 MB
__device__ unsigned long long g_pairs1[(size_t)R1 * R1];   //  8.4 MB

__device__ __forceinline__ float dq(unsigned c) {
    // exact: c/16 - 15/32
    return fmaf((float)c, 0.0625f, -0.46875f);
}

__device__ __forceinline__ unsigned qcode(float x) {
    // codes = clip(round((x - lo)/q), 0, 15); lo = -0.46875, 1/q = 16 (exact)
    float c = rintf(__fmul_rn(__fadd_rn(x, 0.46875f), 16.0f));
    c = fminf(fmaxf(c, 0.0f), 15.0f);
    return (unsigned)c;
}

// 8 channels -> 8 nibbles in a u32
template <int RES>
__device__ __forceinline__ unsigned pack_codes4(const float* __restrict__ g,
                                                size_t idx) {
    const size_t plane = (size_t)RES * RES;
    unsigned packed = 0;
#pragma unroll
    for (int c = 0; c < CCH; c++) {
        float x = __ldg(g + (size_t)c * plane + idx);
        packed |= qcode(x) << (4 * c);
    }
    return packed;
}

template <int RES>
__global__ __launch_bounds__(QTPB) void quant_pack_kernel(
    const float* __restrict__ g, unsigned long long* __restrict__ pairs) {
    size_t idx = (size_t)blockIdx.x * QTPB + threadIdx.x;   // RES*RES % QTPB == 0
    unsigned a = pack_codes4<RES>(g, idx);
    unsigned b = __shfl_down_sync(0xFFFFFFFFu, a, 1);
    if ((threadIdx.x & 31) == 31) {
        size_t j = (idx + 1 < (size_t)RES * RES) ? idx + 1 : idx;
        b = pack_codes4<RES>(g, j);
    }
    pairs[idx] = ((unsigned long long)b << 32) | a;
}

__global__ __launch_bounds__(TPB) void gather_kernel(
    const float2* __restrict__ uv, float* __restrict__ out, int n) {
    __shared__ float buf[TPB * SSTRIDE];
    int i = blockIdx.x * TPB + threadIdx.x;
    int ic = min(i, n - 1);

    float2 p = __ldcs(&uv[ic]);
    float* row = buf + threadIdx.x * SSTRIDE;

    // ---------------- G0: 4-neighbor raw gather ----------------
    float px = __fadd_rn(__fmul_rn(p.x, (float)R0), -0.5f);
    float py = __fadd_rn(__fmul_rn(p.y, (float)R0), -0.5f);
    int x0 = (int)fminf(fmaxf(floorf(px), 0.0f), (float)(R0 - 2));
    int y0 = (int)fminf(fmaxf(floorf(py), 0.0f), (float)(R0 - 2));

    unsigned long long pr0 = __ldg(&g_pairs0[(size_t)y0 * R0 + x0]);
    unsigned long long pr1 = __ldg(&g_pairs0[(size_t)(y0 + 1) * R0 + x0]);
    unsigned c00 = (unsigned)pr0;           // codes(y0, x0)
    unsigned c01 = (unsigned)(pr0 >> 32);   // codes(y0, x1)
    unsigned c10 = (unsigned)pr1;           // codes(y1, x0)
    unsigned c11 = (unsigned)(pr1 >> 32);   // codes(y1, x1)
#pragma unroll
    for (int c = 0; c < CCH; c++) {
        row[c]      = dq((c00 >> (4 * c)) & 0xFu);
        row[8 + c]  = dq((c01 >> (4 * c)) & 0xFu);
        row[16 + c] = dq((c10 >> (4 * c)) & 0xFu);
        row[24 + c] = dq((c11 >> (4 * c)) & 0xFu);
    }

    // ---------------- G1: bilinear grid_sample (zeros pad) ----------------
    // Replicate reference op order exactly (no FMA contraction in index math).
    float gx = __fadd_rn(__fmul_rn(p.x, 2.0f), -1.0f);
    float gy = __fadd_rn(__fmul_rn(p.y, 2.0f), -1.0f);
    float ix = __fadd_rn(__fmul_rn(__fmul_rn(__fadd_rn(gx, 1.0f), 0.5f), (float)R1), -0.5f);
    float iy = __fadd_rn(__fmul_rn(__fmul_rn(__fadd_rn(gy, 1.0f), 0.5f), (float)R1), -0.5f);

    float fx0 = floorf(ix), fy0 = floorf(iy);
    float wx1 = __fadd_rn(ix, -fx0);
    float wy1 = __fadd_rn(iy, -fy0);
    float wx0 = __fadd_rn(1.0f, -wx1);
    float wy0 = __fadd_rn(1.0f, -wy1);

    int jx0 = (int)fx0, jy0 = (int)fy0;
    int jx1 = jx0 + 1, jy1 = jy0 + 1;
    bool vx0 = jx0 >= 0;
    bool vx1 = jx1 <= R1 - 1;
    bool vy0 = jy0 >= 0;
    bool vy1 = jy1 <= R1 - 1;

    float m00 = (vx0 & vy0) ? __fmul_rn(wx0, wy0) : 0.0f;
    float m10 = (vx1 & vy0) ? __fmul_rn(wx1, wy0) : 0.0f;
    float m01 = (vx0 & vy1) ? __fmul_rn(wx0, wy1) : 0.0f;
    float m11 = (vx1 & vy1) ? __fmul_rn(wx1, wy1) : 0.0f;

    int jc  = min(max(jx0, 0), R1 - 1);
    int ry0 = min(max(jy0, 0), R1 - 1);
    int ry1 = min(max(jy1, 0), R1 - 1);

    unsigned long long q0 = __ldg(&g_pairs1[(size_t)ry0 * R1 + jc]);
    unsigned long long q1 = __ldg(&g_pairs1[(size_t)ry1 * R1 + jc]);
    // x0 tap = lo word; x1 tap = hi word, except jx0==-1 where x1 -> col0 = lo
    unsigned t00 = (unsigned)q0;
    unsigned t10 = (jx0 < 0) ? (unsigned)q0 : (unsigned)(q0 >> 32);
    unsigned t01 = (unsigned)q1;
    unsigned t11 = (jx0 < 0) ? (unsigned)q1 : (unsigned)(q1 >> 32);

#pragma unroll
    for (int c = 0; c < CCH; c++) {
        float acc = 0.0f;
        acc = fmaf(dq((t00 >> (4 * c)) & 0xFu), m00, acc);
        acc = fmaf(dq((t10 >> (4 * c)) & 0xFu), m10, acc);
        acc = fmaf(dq((t01 >> (4 * c)) & 0xFu), m01, acc);
        acc = fmaf(dq((t11 >> (4 * c)) & 0xFu), m11, acc);
        row[32 + c] = acc;
    }

    __syncthreads();

    // ---------------- coalesced streaming store ----------------
    // TPB=320 is a multiple of 40 -> pp/cc split is loop-invariant in k.
    int tq = threadIdx.x / 40;       // point sub-index base
    int cc = threadIdx.x - tq * 40;  // feature index (constant per thread)
    size_t base = (size_t)blockIdx.x * TPB * 40 + threadIdx.x;
    size_t total = (size_t)n * 40;
#pragma unroll
    for (int k = 0; k < 40; k++) {
        int pp = 8 * k + tq;                 // (k*320 + tid) / 40
        size_t g = base + (size_t)k * TPB;   // (k*320 + tid) linear offset
        if (g < total) __stcs(out + g, buf[pp * SSTRIDE + cc]);
    }
}

extern "C" void kernel_launch(void* const* d_in, const int* in_sizes, int n_in,
                              void* d_out, int out_size) {
    const float* uv = (const float*)d_in[0];
    const float* g0 = (const float*)d_in[1];
    const float* g1 = (const float*)d_in[2];
    float* out = (float*)d_out;

    int n = in_sizes[0] / 2;

    unsigned long long* p0;
    unsigned long long* p1;
    cudaGetSymbolAddress((void**)&p0, g_pairs0);
    cudaGetSymbolAddress((void**)&p1, g_pairs1);

    quant_pack_kernel<R0><<<(R0 * R0) / QTPB, QTPB>>>(g0, p0);
    quant_pack_kernel<R1><<<(R1 * R1) / QTPB, QTPB>>>(g1, p1);

    gather_kernel<<<(n + TPB - 1) / TPB, TPB>>>((const float2*)uv, out, n);
}